// round 16
// baseline (speedup 1.0000x reference)
#include <cuda_runtime.h>
#include <cstdint>

// Problem constants (fixed shapes for this problem)
#define Bc 8
#define Hc 1024
#define Ec 512
#define Vc 32000
#define Tc 100
#define KVc 1536   // H + E   (x_v width)
#define KKc 2560   // 2H + E  (x_k width)

#define GRID_MAIN 444          // 3 blocks per SM on 148 SMs, single wave
// 8000 tiles = 444*18 + 8 -> first 8 blocks take 19 tiles, rest 18

// Scratch (device globals; zero-initialized at module load, no runtime alloc)
__device__ int   g_cnt[Bc * Vc];               // topic word counts (kept zero between runs)
__device__ float g_ekval[Bc * Vc];             // e_k values (valid only where cnt>0)
__device__ float g_psum[GRID_MAIN * Bc];       // per-BLOCK partial softmax sums

// ---------------------------------------------------------------------------
// Kernel 1: count topic words + compute e_k for each (b, topic word) pair.
// 4 warps per pair (each covers 640 of 2560 cols), smem combine. 800 pairs ->
// 400 blocks x 256 threads (2 pairs per block).   [proven R5]
// ---------------------------------------------------------------------------
__global__ void __launch_bounds__(256) count_ek_kernel(const int*   __restrict__ topics,
                                                       const float* __restrict__ outp,
                                                       const float* __restrict__ inp,
                                                       const float* __restrict__ ctx,
                                                       const float* __restrict__ WK,
                                                       const float* __restrict__ bK) {
    __shared__ float part[2][4];

    int tid  = threadIdx.x;
    int warp = tid >> 5;
    int lane = tid & 31;
    int lp   = warp >> 2;        // local pair 0/1
    int q    = warp & 3;         // quarter of the 2560-dot
    int pair = blockIdx.x * 2 + lp;

    int b   = pair / Tc;
    int idx = topics[pair];

    float s = 0.f;
    if (idx != 0) {
        const float* wrow = WK + (size_t)idx * KKc + q * 640;
        int cbase = q * 640 + lane * 4;
        #pragma unroll
        for (int i = 0; i < 5; i++) {
            int cc = cbase + i * 128;
            float4 wv = *(const float4*)(wrow + lane * 4 + i * 128);
            float4 xv;
            if (cc < Hc)            xv = *(const float4*)(outp + b * Hc + cc);
            else if (cc < Hc + Ec)  xv = *(const float4*)(inp  + b * Ec + (cc - Hc));
            else                    xv = *(const float4*)(ctx  + b * Hc + (cc - Hc - Ec));
            s += wv.x * xv.x + wv.y * xv.y + wv.z * xv.z + wv.w * xv.w;
        }
        #pragma unroll
        for (int h = 16; h >= 1; h >>= 1) s += __shfl_xor_sync(0xffffffffu, s, h);
    }
    if (lane == 0) part[lp][q] = s;
    __syncthreads();

    if (tid < 2) {
        int p2 = blockIdx.x * 2 + tid;
        int b2 = p2 / Tc;
        int i2 = topics[p2];
        if (i2 != 0) {
            float e = part[tid][0] + part[tid][1] + part[tid][2] + part[tid][3];
            atomicAdd(&g_cnt[b2 * Vc + i2], 1);
            g_ekval[b2 * Vc + i2] = e + bK[i2];   // duplicates write identical values
        }
    }
}

// ---------------------------------------------------------------------------
// Kernel 2: main GEMV + gate + tanh + exp + block-level partial sums.
// 4 rows x 8 batches per warp-tile, SINGLE-buffered W loads (no explicit
// prefetch regs -> ~66 live regs) capped at 84 via launch_bounds(256,3):
// 3 blocks/SM, 24 warps/SM for inter-warp latency hiding.
// ---------------------------------------------------------------------------
__global__ void __launch_bounds__(256, 3) main_kernel(const float* __restrict__ outp,
                                                      const float* __restrict__ inp,
                                                      const float* __restrict__ WV,
                                                      const float* __restrict__ bV,
                                                      float* __restrict__ out) {
    __shared__ float xs[Bc * KVc];   // 49152 bytes (exactly 48 KB)
    __shared__ float sm_ps[8 * Bc];  // per-warp batch sums

    int tid  = threadIdx.x;
    int warp = tid >> 5;
    int lane = tid & 31;

    // cooperative fill of x_v = concat(output, input_step) per batch
    for (int i = tid; i < (Bc * KVc) / 4; i += 256) {
        int fi = i * 4;
        int b = fi / KVc;
        int c = fi % KVc;
        float4 v;
        if (c < Hc) v = *(const float4*)(outp + b * Hc + c);
        else        v = *(const float4*)(inp  + b * Ec + (c - Hc));
        *(float4*)(xs + fi) = v;
    }
    __syncthreads();

    int b = lane & 7;
    int r = lane >> 3;
    float lsum = 0.f;

    int blk   = blockIdx.x;
    int tbase = blk * 18 + (blk < 8 ? blk : 8);
    int tcnt  = 18 + (blk < 8 ? 1 : 0);

    #pragma unroll 1
    for (int k = warp; k < tcnt; k += 8) {
        int tile = tbase + k;
        int w0 = tile * 4;
        float acc[32];
        #pragma unroll
        for (int j = 0; j < 32; j++) acc[j] = 0.f;

        const float* Wp = WV + (size_t)w0 * KVc + lane * 4;

        #pragma unroll 2
        for (int it = 0; it < 12; it++) {
            int cb = it * 128;
            float4 w0v = *(const float4*)(Wp + cb);
            float4 w1v = *(const float4*)(Wp + KVc + cb);
            float4 w2v = *(const float4*)(Wp + 2 * KVc + cb);
            float4 w3v = *(const float4*)(Wp + 3 * KVc + cb);
            int xb = cb + lane * 4;
            #pragma unroll
            for (int bb = 0; bb < 8; bb++) {
                float4 xv = *(const float4*)(xs + bb * KVc + xb);
                acc[0 * 8 + bb] = fmaf(w0v.x, xv.x, acc[0 * 8 + bb]);
                acc[0 * 8 + bb] = fmaf(w0v.y, xv.y, acc[0 * 8 + bb]);
                acc[0 * 8 + bb] = fmaf(w0v.z, xv.z, acc[0 * 8 + bb]);
                acc[0 * 8 + bb] = fmaf(w0v.w, xv.w, acc[0 * 8 + bb]);
                acc[1 * 8 + bb] = fmaf(w1v.x, xv.x, acc[1 * 8 + bb]);
                acc[1 * 8 + bb] = fmaf(w1v.y, xv.y, acc[1 * 8 + bb]);
                acc[1 * 8 + bb] = fmaf(w1v.z, xv.z, acc[1 * 8 + bb]);
                acc[1 * 8 + bb] = fmaf(w1v.w, xv.w, acc[1 * 8 + bb]);
                acc[2 * 8 + bb] = fmaf(w2v.x, xv.x, acc[2 * 8 + bb]);
                acc[2 * 8 + bb] = fmaf(w2v.y, xv.y, acc[2 * 8 + bb]);
                acc[2 * 8 + bb] = fmaf(w2v.z, xv.z, acc[2 * 8 + bb]);
                acc[2 * 8 + bb] = fmaf(w2v.w, xv.w, acc[2 * 8 + bb]);
                acc[3 * 8 + bb] = fmaf(w3v.x, xv.x, acc[3 * 8 + bb]);
                acc[3 * 8 + bb] = fmaf(w3v.y, xv.y, acc[3 * 8 + bb]);
                acc[3 * 8 + bb] = fmaf(w3v.z, xv.z, acc[3 * 8 + bb]);
                acc[3 * 8 + bb] = fmaf(w3v.w, xv.w, acc[3 * 8 + bb]);
            }
        }

        // butterfly transpose-reduce: 31 shuffles; lane l ends with sum of acc[l]
        #pragma unroll
        for (int h = 16; h >= 1; h >>= 1) {
            #pragma unroll
            for (int j = 0; j < h; j++) {
                float lo = acc[j];
                float hi = acc[j + h];
                float mine = (lane & h) ? hi : lo;
                float send = (lane & h) ? lo : hi;
                float recv = __shfl_xor_sync(0xffffffffu, send, h);
                acc[j] = mine + recv;
            }
        }

        int w = w0 + r;
        float ev = acc[0] + __ldg(bV + w);
        int cnt = g_cnt[b * Vc + w];
        float en = (cnt == 0) ? ev : (float)cnt * g_ekval[b * Vc + w];
        en = tanhf(en);
        float p = __expf(en);
        out[b * Vc + w] = p;
        lsum += p;
    }

    // lanes {l, l^8, l^16, l^24} share batch b = l&7 -> combine, lane<8 writes
    lsum += __shfl_xor_sync(0xffffffffu, lsum, 8);
    lsum += __shfl_xor_sync(0xffffffffu, lsum, 16);
    if (lane < 8) sm_ps[warp * 8 + b] = lsum;
    __syncthreads();

    // block-level deterministic combine: 8 warps -> one value per batch
    if (tid < 8) {
        float s = 0.f;
        #pragma unroll
        for (int wv = 0; wv < 8; wv++) s += sm_ps[wv * 8 + tid];
        g_psum[blockIdx.x * 8 + tid] = s;
    }
}

// ---------------------------------------------------------------------------
// Kernel 3: fused reduce + normalize + g_cnt cleanup.
// grid (125, 8), 256 threads. Each block redundantly (deterministically)
// reduces the 444 per-block partials for its batch (L2-resident), then
// normalizes its 256-element slice. Blocks at x==0 re-zero the g_cnt entries
// touched by this run, restoring the all-zero invariant for the next replay.
// ---------------------------------------------------------------------------
__global__ void norm_kernel(float* __restrict__ out, const int* __restrict__ topics) {
    int b = blockIdx.y;
    int tid = threadIdx.x;
    __shared__ float ssum[8];
    __shared__ float srinv;

    float s = 0.f;
    if (tid < GRID_MAIN)       s += g_psum[tid * 8 + b];
    if (tid + 256 < GRID_MAIN) s += g_psum[(tid + 256) * 8 + b];
    #pragma unroll
    for (int h = 16; h >= 1; h >>= 1) s += __shfl_xor_sync(0xffffffffu, s, h);
    if ((tid & 31) == 0) ssum[tid >> 5] = s;
    __syncthreads();
    if (tid == 0) {
        float t = 0.f;
        #pragma unroll
        for (int w = 0; w < 8; w++) t += ssum[w];
        srinv = 1.0f / t;
    }
    __syncthreads();

    // cleanup: restore g_cnt to all-zero (indices touched this run only)
    if (blockIdx.x == 0) {
        for (int t = tid; t < Tc; t += 256)
            g_cnt[b * Vc + topics[b * Tc + t]] = 0;
    }

    int i = blockIdx.x * 256 + tid;   // 125*256 == 32000 exactly
    out[b * Vc + i] *= srinv;
}

// ---------------------------------------------------------------------------
// Launch (3 kernels)
// Input order: output, input_step, context, topic_indexs, [topic_length],
//              W_V, b_V, W_K, b_K
// ---------------------------------------------------------------------------
extern "C" void kernel_launch(void* const* d_in, const int* in_sizes, int n_in,
                              void* d_out, int out_size) {
    const float* outp   = (const float*)d_in[0];
    const float* inp    = (const float*)d_in[1];
    const float* ctx    = (const float*)d_in[2];
    const int*   topics = (const int*)d_in[3];

    int base = 4;
    if (n_in >= 9 && in_sizes[4] <= 4) base = 5;   // skip topic_length scalar

    const float* WV = (const float*)d_in[base + 0];
    const float* bV = (const float*)d_in[base + 1];
    const float* WK = (const float*)d_in[base + 2];
    const float* bK = (const float*)d_in[base + 3];
    float* out = (float*)d_out;

    count_ek_kernel<<<(Bc * Tc) / 2, 256>>>(topics, outp, inp, ctx, WK, bK);
    main_kernel<<<GRID_MAIN, 256>>>(outp, inp, WV, bV, out);
    norm_kernel<<<dim3(Vc / 256, Bc), 256>>>(out, topics);
}